// round 2
// baseline (speedup 1.0000x reference)
#include <cuda_runtime.h>
#include <cuda_bf16.h>

// ---------------------------------------------------------------------------
// Florence2 window attention, fp32 baseline.
// Shapes: hidden (8,48,48,512), qkv_w (512,1536), proj_w (512,512)
// WINDOW=12 -> 128 windows x 144 tokens. 16 heads x 32 dim.
// ---------------------------------------------------------------------------

#define NWIN   128          // 8 * 4 * 4
#define NTOK   144          // 12 * 12
#define DIM    512
#define NHEAD  16
#define HDIM   32
#define MTOT   (NWIN * NTOK)     // 18432

// Scratch (device globals; no allocation allowed)
__device__ float g_q[NWIN * NHEAD * NTOK * HDIM];   // [win*16+head][tok][d]
__device__ float g_k[NWIN * NHEAD * NTOK * HDIM];
__device__ float g_v[NWIN * NHEAD * NTOK * HDIM];
__device__ float g_ao[MTOT * DIM];                  // [win*144+tok][c]

// ---------------------------------------------------------------------------
// SGEMM tiling: 128x128x8, 256 threads, 8x8 microtile, double-buffered smem
// ---------------------------------------------------------------------------
#define BM 128
#define BN 128
#define BK 8

// map window-order row m -> global memory row offset of hidden_states
__device__ __forceinline__ int hidden_row_off(int m) {
    int win = m / NTOK, t = m % NTOK;
    int b = win >> 4, yw = (win >> 2) & 3, xw = win & 3;
    int y = yw * 12 + t / 12;
    int x = xw * 12 + t % 12;
    return ((b * 48 + y) * 48 + x) * DIM;
}

// ---------------------------------------------------------------------------
// Kernel 1: QKV GEMM.  C[m][n] = X[m][:] . W[:][n] + b[n]
// A is gathered in window order; epilogue scatters into g_q/g_k/g_v
// layout [ (win*16+head) ][ tok ][ d ]
// ---------------------------------------------------------------------------
__global__ __launch_bounds__(256, 2)
void qkv_gemm_kernel(const float* __restrict__ X,
                     const float* __restrict__ W,
                     const float* __restrict__ bias)
{
    __shared__ float As[2][BK][BM + 4];
    __shared__ float Bs[2][BK][BN];

    const int tid = threadIdx.x;
    const int m0 = blockIdx.y * BM;
    const int n0 = blockIdx.x * BN;

    // ---- A load: each thread loads float4 (row = tid/2, k4 = (tid&1)*4) ----
    const int a_row = tid >> 1;
    const int a_k   = (tid & 1) << 2;
    const float* a_ptr = X + hidden_row_off(m0 + a_row) + a_k;

    // ---- B load: float4 (krow = tid/32, col = (tid&31)*4), W stride 1536 ---
    const int b_k   = tid >> 5;
    const int b_col = (tid & 31) << 2;
    const float* b_ptr = W + b_k * 1536 + n0 + b_col;

    // prologue: tile 0 -> buffer 0
    {
        float4 av = *(const float4*)a_ptr;
        float4 bv = *(const float4*)b_ptr;
        As[0][a_k + 0][a_row] = av.x;
        As[0][a_k + 1][a_row] = av.y;
        As[0][a_k + 2][a_row] = av.z;
        As[0][a_k + 3][a_row] = av.w;
        *(float4*)&Bs[0][b_k][b_col] = bv;
    }
    __syncthreads();

    float acc[8][8] = {};
    const int ty = tid >> 4, tx = tid & 15;
    const int row_c = ty * 8, col_c = tx * 8;

    const int KT = DIM / BK;   // 64
    for (int kt = 0; kt < KT; ++kt) {
        const int cur = kt & 1;
        float4 na, nb;
        if (kt + 1 < KT) {
            na = *(const float4*)(a_ptr + (kt + 1) * BK);
            nb = *(const float4*)(b_ptr + (kt + 1) * BK * 1536);
        }
        #pragma unroll
        for (int kk = 0; kk < BK; ++kk) {
            float4 a0 = *(const float4*)&As[cur][kk][row_c];
            float4 a1 = *(const float4*)&As[cur][kk][row_c + 4];
            float4 b0 = *(const float4*)&Bs[cur][kk][col_c];
            float4 b1 = *(const float4*)&Bs[cur][kk][col_c + 4];
            float ar[8] = {a0.x, a0.y, a0.z, a0.w, a1.x, a1.y, a1.z, a1.w};
            float br[8] = {b0.x, b0.y, b0.z, b0.w, b1.x, b1.y, b1.z, b1.w};
            #pragma unroll
            for (int i = 0; i < 8; ++i)
                #pragma unroll
                for (int j = 0; j < 8; ++j)
                    acc[i][j] = fmaf(ar[i], br[j], acc[i][j]);
        }
        if (kt + 1 < KT) {
            const int nxt = cur ^ 1;
            As[nxt][a_k + 0][a_row] = na.x;
            As[nxt][a_k + 1][a_row] = na.y;
            As[nxt][a_k + 2][a_row] = na.z;
            As[nxt][a_k + 3][a_row] = na.w;
            *(float4*)&Bs[nxt][b_k][b_col] = nb;
        }
        __syncthreads();
    }

    // ---- epilogue: bias + scatter to q/k/v [wh][tok][d] ----
    #pragma unroll
    for (int i = 0; i < 8; ++i) {
        const int m = m0 + row_c + i;
        const int win = m / NTOK, t = m % NTOK;
        #pragma unroll
        for (int jj = 0; jj < 8; jj += 4) {
            const int n = n0 + col_c + jj;
            const int sel  = n >> 9;          // 0=q 1=k 2=v
            const int head = (n >> 5) & 15;
            const int d    = n & 31;
            float* dst = (sel == 0) ? g_q : (sel == 1) ? g_k : g_v;
            float4 v;
            v.x = acc[i][jj + 0] + bias[n + 0];
            v.y = acc[i][jj + 1] + bias[n + 1];
            v.z = acc[i][jj + 2] + bias[n + 2];
            v.w = acc[i][jj + 3] + bias[n + 3];
            *(float4*)&dst[(((win << 4) + head) * NTOK + t) * HDIM + d] = v;
        }
    }
}

// ---------------------------------------------------------------------------
// Kernel 2: attention. one block per (win,head). K/V staged in smem,
// one thread per query row, single-pass exp (scores are small: |s| < ~3).
// ---------------------------------------------------------------------------
__global__ __launch_bounds__(160, 4)
void attn_kernel()
{
    __shared__ float Ks[NTOK * HDIM];   // 18.4 KB
    __shared__ float Vs[NTOK * HDIM];   // 18.4 KB

    const int wh = blockIdx.x;          // win*16 + head
    const int tid = threadIdx.x;
    const float* kp = g_k + wh * (NTOK * HDIM);
    const float* vp = g_v + wh * (NTOK * HDIM);

    for (int i = tid; i < NTOK * HDIM / 4; i += 160) {
        ((float4*)Ks)[i] = ((const float4*)kp)[i];
        ((float4*)Vs)[i] = ((const float4*)vp)[i];
    }
    __syncthreads();

    if (tid < NTOK) {
        float q[HDIM];
        const float* qp = g_q + wh * (NTOK * HDIM) + tid * HDIM;
        #pragma unroll
        for (int d4 = 0; d4 < HDIM / 4; ++d4) {
            float4 v = ((const float4*)qp)[d4];
            q[d4 * 4 + 0] = v.x; q[d4 * 4 + 1] = v.y;
            q[d4 * 4 + 2] = v.z; q[d4 * 4 + 3] = v.w;
        }

        float acc[HDIM] = {};
        float sum = 0.f;
        const float scale = 0.1767766952966369f;   // 32^-0.5

        for (int j = 0; j < NTOK; ++j) {
            const float4* kr = (const float4*)&Ks[j * HDIM];
            float s = 0.f;
            #pragma unroll
            for (int d4 = 0; d4 < HDIM / 4; ++d4) {
                float4 kv = kr[d4];
                s = fmaf(q[d4 * 4 + 0], kv.x, s);
                s = fmaf(q[d4 * 4 + 1], kv.y, s);
                s = fmaf(q[d4 * 4 + 2], kv.z, s);
                s = fmaf(q[d4 * 4 + 3], kv.w, s);
            }
            const float e = __expf(s * scale);
            sum += e;
            const float4* vr = (const float4*)&Vs[j * HDIM];
            #pragma unroll
            for (int d4 = 0; d4 < HDIM / 4; ++d4) {
                float4 vv = vr[d4];
                acc[d4 * 4 + 0] = fmaf(e, vv.x, acc[d4 * 4 + 0]);
                acc[d4 * 4 + 1] = fmaf(e, vv.y, acc[d4 * 4 + 1]);
                acc[d4 * 4 + 2] = fmaf(e, vv.z, acc[d4 * 4 + 2]);
                acc[d4 * 4 + 3] = fmaf(e, vv.w, acc[d4 * 4 + 3]);
            }
        }

        const float inv = 1.f / sum;
        const int win = wh >> 4, head = wh & 15;
        float* op = g_ao + (win * NTOK + tid) * DIM + head * HDIM;
        #pragma unroll
        for (int d4 = 0; d4 < HDIM / 4; ++d4) {
            float4 v;
            v.x = acc[d4 * 4 + 0] * inv;
            v.y = acc[d4 * 4 + 1] * inv;
            v.z = acc[d4 * 4 + 2] * inv;
            v.w = acc[d4 * 4 + 3] * inv;
            ((float4*)op)[d4] = v;
        }
    }
}

// ---------------------------------------------------------------------------
// Kernel 3: proj GEMM + window_reverse scatter into final (b, h*w, c) output.
// ---------------------------------------------------------------------------
__global__ __launch_bounds__(256, 2)
void proj_gemm_kernel(const float* __restrict__ W,
                      const float* __restrict__ bias,
                      float* __restrict__ out)
{
    __shared__ float As[2][BK][BM + 4];
    __shared__ float Bs[2][BK][BN];

    const int tid = threadIdx.x;
    const int m0 = blockIdx.y * BM;
    const int n0 = blockIdx.x * BN;

    const int a_row = tid >> 1;
    const int a_k   = (tid & 1) << 2;
    const float* a_ptr = g_ao + (m0 + a_row) * DIM + a_k;

    const int b_k   = tid >> 5;
    const int b_col = (tid & 31) << 2;
    const float* b_ptr = W + b_k * DIM + n0 + b_col;

    {
        float4 av = *(const float4*)a_ptr;
        float4 bv = *(const float4*)b_ptr;
        As[0][a_k + 0][a_row] = av.x;
        As[0][a_k + 1][a_row] = av.y;
        As[0][a_k + 2][a_row] = av.z;
        As[0][a_k + 3][a_row] = av.w;
        *(float4*)&Bs[0][b_k][b_col] = bv;
    }
    __syncthreads();

    float acc[8][8] = {};
    const int ty = tid >> 4, tx = tid & 15;
    const int row_c = ty * 8, col_c = tx * 8;

    const int KT = DIM / BK;
    for (int kt = 0; kt < KT; ++kt) {
        const int cur = kt & 1;
        float4 na, nb;
        if (kt + 1 < KT) {
            na = *(const float4*)(a_ptr + (kt + 1) * BK);
            nb = *(const float4*)(b_ptr + (kt + 1) * BK * DIM);
        }
        #pragma unroll
        for (int kk = 0; kk < BK; ++kk) {
            float4 a0 = *(const float4*)&As[cur][kk][row_c];
            float4 a1 = *(const float4*)&As[cur][kk][row_c + 4];
            float4 b0 = *(const float4*)&Bs[cur][kk][col_c];
            float4 b1 = *(const float4*)&Bs[cur][kk][col_c + 4];
            float ar[8] = {a0.x, a0.y, a0.z, a0.w, a1.x, a1.y, a1.z, a1.w};
            float br[8] = {b0.x, b0.y, b0.z, b0.w, b1.x, b1.y, b1.z, b1.w};
            #pragma unroll
            for (int i = 0; i < 8; ++i)
                #pragma unroll
                for (int j = 0; j < 8; ++j)
                    acc[i][j] = fmaf(ar[i], br[j], acc[i][j]);
        }
        if (kt + 1 < KT) {
            const int nxt = cur ^ 1;
            As[nxt][a_k + 0][a_row] = na.x;
            As[nxt][a_k + 1][a_row] = na.y;
            As[nxt][a_k + 2][a_row] = na.z;
            As[nxt][a_k + 3][a_row] = na.w;
            *(float4*)&Bs[nxt][b_k][b_col] = nb;
        }
        __syncthreads();
    }

    // epilogue: bias + window_reverse scatter
    #pragma unroll
    for (int i = 0; i < 8; ++i) {
        const int m = m0 + row_c + i;
        const int win = m / NTOK, t = m % NTOK;
        const int b = win >> 4, yw = (win >> 2) & 3, xw = win & 3;
        const int y = yw * 12 + t / 12;
        const int x = xw * 12 + t % 12;
        float* orow = out + ((b * 2304 + y * 48 + x) << 9);
        #pragma unroll
        for (int jj = 0; jj < 8; jj += 4) {
            const int n = n0 + col_c + jj;
            float4 v;
            v.x = acc[i][jj + 0] + bias[n + 0];
            v.y = acc[i][jj + 1] + bias[n + 1];
            v.z = acc[i][jj + 2] + bias[n + 2];
            v.w = acc[i][jj + 3] + bias[n + 3];
            *(float4*)&orow[n] = v;
        }
    }
}

// ---------------------------------------------------------------------------
extern "C" void kernel_launch(void* const* d_in, const int* in_sizes, int n_in,
                              void* d_out, int out_size)
{
    const float* hidden = (const float*)d_in[0];
    const float* qkv_w  = (const float*)d_in[1];
    const float* qkv_b  = (const float*)d_in[2];
    const float* proj_w = (const float*)d_in[3];
    const float* proj_b = (const float*)d_in[4];
    float* out = (float*)d_out;

    dim3 blk(256);
    dim3 grid_qkv(1536 / BN, MTOT / BM);     // 12 x 144
    qkv_gemm_kernel<<<grid_qkv, blk>>>(hidden, qkv_w, qkv_b);

    attn_kernel<<<NWIN * NHEAD, 160>>>();    // 2048 blocks

    dim3 grid_proj(DIM / BN, MTOT / BM);     // 4 x 144
    proj_gemm_kernel<<<grid_proj, blk>>>(proj_w, proj_b, out);
}

// round 6
// speedup vs baseline: 2.5838x; 2.5838x over previous
#include <cuda_runtime.h>
#include <cuda_fp16.h>
#include <cstdint>

// ---------------------------------------------------------------------------
// Florence2 window attention.
// GEMMs: fp16 mma.sync.m16n8k16 (fp32 accum). Conservative datapath:
//   LDG->reg->STS staging, padded smem rows (no swizzle),
//   direct LDS.32 fragment loads (no ldmatrix).
// Attention: fp32 FMA (proven round-2 kernel).
// NOTE: device-global scratch is only ever referenced from DEVICE code
// (passing __device__ arrays as kernel args from host was the R4/R5 bug).
// ---------------------------------------------------------------------------

#define NWIN   128
#define NTOK   144
#define DIM    512
#define NHEAD  16
#define HDIM   32
#define MTOT   (NWIN * NTOK)     // 18432
#define NQKV   1536

#define SROW   72                // smem row stride in halves (144B, 9x16B)

// ---------------- scratch (device globals; no allocs allowed) --------------
__device__ __align__(16) __half g_x [MTOT * DIM];   // window-gathered X [m][k]
__device__ __align__(16) __half g_wq[NQKV * DIM];   // qkv_w transposed [n][k]
__device__ __align__(16) __half g_wp[DIM * DIM];    // proj_w transposed [n][k]
__device__ __align__(16) float g_q[NWIN * NHEAD * NTOK * HDIM];
__device__ __align__(16) float g_k[NWIN * NHEAD * NTOK * HDIM];
__device__ __align__(16) float g_v[NWIN * NHEAD * NTOK * HDIM];
__device__ __align__(16) __half g_ao[MTOT * DIM];   // attention out [m][k]

// ---------------- mma.sync helper ------------------------------------------
__device__ __forceinline__ void mma16816(float* d, const uint32_t* a,
                                         uint32_t b0, uint32_t b1) {
    asm volatile("mma.sync.aligned.m16n8k16.row.col.f32.f16.f16.f32 "
        "{%0,%1,%2,%3}, {%4,%5,%6,%7}, {%8,%9}, {%0,%1,%2,%3};"
        : "+f"(d[0]), "+f"(d[1]), "+f"(d[2]), "+f"(d[3])
        : "r"(a[0]), "r"(a[1]), "r"(a[2]), "r"(a[3]), "r"(b0), "r"(b1));
}

// map window-order row m -> gmem row offset of hidden_states
__device__ __forceinline__ int hidden_row_off(int m) {
    int win = m / NTOK, t = m % NTOK;
    int b = win >> 4, yw = (win >> 2) & 3, xw = win & 3;
    int y = yw * 12 + t / 12;
    int x = xw * 12 + t % 12;
    return ((b * 48 + y) * 48 + x) * DIM;
}

// ---------------------------------------------------------------------------
// conversion kernels (fp32 -> fp16)
// ---------------------------------------------------------------------------
__global__ void convert_x_kernel(const float* __restrict__ hidden) {
    int idx = blockIdx.x * 256 + threadIdx.x;       // m*64 + seg
    int m = idx >> 6, seg = idx & 63;
    const float* src = hidden + hidden_row_off(m) + seg * 8;
    float4 f0 = *(const float4*)src;
    float4 f1 = *(const float4*)(src + 4);
    __align__(16) __half h[8];
    h[0] = __float2half(f0.x); h[1] = __float2half(f0.y);
    h[2] = __float2half(f0.z); h[3] = __float2half(f0.w);
    h[4] = __float2half(f1.x); h[5] = __float2half(f1.y);
    h[6] = __float2half(f1.z); h[7] = __float2half(f1.w);
    *(uint4*)&g_x[m * DIM + seg * 8] = *(uint4*)h;
}

// transpose W [K=512][N] -> [n][512] fp16.
// sel: 0 -> qkv weights (N=1536) into g_wq; 1 -> proj weights (N=512) into g_wp.
// Destination resolved in DEVICE code (host cannot pass __device__ arrays).
__global__ void convert_w_kernel(const float* __restrict__ W, int sel) {
    __shared__ float t[32][33];
    const int N = sel ? DIM : NQKV;
    __half* __restrict__ outT = sel ? g_wp : g_wq;
    int tx = threadIdx.x, ty = threadIdx.y;
    int n0 = blockIdx.x * 32, k0 = blockIdx.y * 32;
    #pragma unroll
    for (int j = 0; j < 4; ++j)
        t[ty + 8 * j][tx] = W[(k0 + ty + 8 * j) * N + n0 + tx];
    __syncthreads();
    #pragma unroll
    for (int j = 0; j < 4; ++j)
        outT[(n0 + ty + 8 * j) * DIM + k0 + tx] = __float2half(t[tx][ty + 8 * j]);
}

// ---------------------------------------------------------------------------
// HGEMM mainloop: 128x128 CTA tile, K=512 in 8 chunks of 64.
// LDG->reg->STS staged. 8 warps: warp tile 32(M) x 64(N).
// A [m][k], B [n][k] fp16. Direct LDS.32 fragment loads (PTX m16n8k16 layout).
// ---------------------------------------------------------------------------
__device__ __forceinline__ void hgemm_tile(
    const __half* __restrict__ A, const __half* __restrict__ B,
    int m0, int n0, float acc[2][8][4])
{
    __shared__ __align__(16) __half sA[128 * SROW];   // 18432 B
    __shared__ __align__(16) __half sB[128 * SROW];   // 18432 B

    const int tid = threadIdx.x;
    const int lane = tid & 31, wid = tid >> 5;
    const int g = lane >> 2, t = lane & 3;
    const int wm = (wid & 3) * 32, wn = (wid >> 2) * 64;

    // staging coords: 4 x 16B segments per operand per thread
    int rowv[4], uv[4];
    #pragma unroll
    for (int i = 0; i < 4; ++i) {
        rowv[i] = 32 * i + (tid >> 3);
        uv[i]   = tid & 7;
    }

    uint4 rga[4], rgb[4];
    #pragma unroll
    for (int i = 0; i < 4; ++i) {       // prefetch chunk 0
        rga[i] = *(const uint4*)(A + (m0 + rowv[i]) * DIM + uv[i] * 8);
        rgb[i] = *(const uint4*)(B + (n0 + rowv[i]) * DIM + uv[i] * 8);
    }

    #pragma unroll 1
    for (int ch = 0; ch < 8; ++ch) {
        #pragma unroll
        for (int i = 0; i < 4; ++i) {
            *(uint4*)&sA[rowv[i] * SROW + uv[i] * 8] = rga[i];
            *(uint4*)&sB[rowv[i] * SROW + uv[i] * 8] = rgb[i];
        }
        __syncthreads();

        if (ch < 7) {                   // prefetch next chunk into registers
            const int ko = (ch + 1) * 64;
            #pragma unroll
            for (int i = 0; i < 4; ++i) {
                rga[i] = *(const uint4*)(A + (m0 + rowv[i]) * DIM + ko + uv[i] * 8);
                rgb[i] = *(const uint4*)(B + (n0 + rowv[i]) * DIM + ko + uv[i] * 8);
            }
        }

        #pragma unroll
        for (int s = 0; s < 4; ++s) {
            const int k0 = s * 16 + 2 * t;
            uint32_t a[2][4];
            #pragma unroll
            for (int i = 0; i < 2; ++i) {
                const int r = wm + i * 16 + g;
                a[i][0] = *(const uint32_t*)&sA[ r      * SROW + k0    ];
                a[i][1] = *(const uint32_t*)&sA[(r + 8) * SROW + k0    ];
                a[i][2] = *(const uint32_t*)&sA[ r      * SROW + k0 + 8];
                a[i][3] = *(const uint32_t*)&sA[(r + 8) * SROW + k0 + 8];
            }
            #pragma unroll
            for (int j = 0; j < 8; ++j) {
                const int rn = wn + j * 8 + g;
                uint32_t b0 = *(const uint32_t*)&sB[rn * SROW + k0    ];
                uint32_t b1 = *(const uint32_t*)&sB[rn * SROW + k0 + 8];
                mma16816(acc[0][j], a[0], b0, b1);
                mma16816(acc[1][j], a[1], b0, b1);
            }
        }
        __syncthreads();
    }
}

// ---------------------------------------------------------------------------
// Kernel: QKV GEMM. epilogue: +bias, scatter to g_q/g_k/g_v [wh][tok][d]
// ---------------------------------------------------------------------------
__global__ __launch_bounds__(256, 2)
void qkv_hgemm_kernel(const float* __restrict__ bias)
{
    float acc[2][8][4] = {};
    const int m0 = blockIdx.y * 128, n0 = blockIdx.x * 128;
    hgemm_tile(g_x, g_wq, m0, n0, acc);

    const int tid = threadIdx.x, lane = tid & 31, wid = tid >> 5;
    const int g = lane >> 2, t = lane & 3;
    const int wm = (wid & 3) * 32, wn = (wid >> 2) * 64;

    #pragma unroll
    for (int i = 0; i < 2; ++i) {
        #pragma unroll
        for (int h = 0; h < 2; ++h) {
            const int m = m0 + wm + i * 16 + h * 8 + g;
            const int win = m / NTOK, tok = m % NTOK;
            #pragma unroll
            for (int j = 0; j < 8; ++j) {
                const int n = n0 + wn + j * 8 + 2 * t;
                const int sel = n >> 9, head = (n >> 5) & 15, d = n & 31;
                float* dst = (sel == 0) ? g_q : (sel == 1) ? g_k : g_v;
                float2 v;
                v.x = acc[i][j][h * 2 + 0] + bias[n + 0];
                v.y = acc[i][j][h * 2 + 1] + bias[n + 1];
                *(float2*)&dst[(((win << 4) + head) * NTOK + tok) * HDIM + d] = v;
            }
        }
    }
}

// ---------------------------------------------------------------------------
// Kernel: attention (fp32, proven). epilogue writes fp16 g_ao for proj GEMM.
// ---------------------------------------------------------------------------
__global__ __launch_bounds__(160, 4)
void attn_kernel()
{
    __shared__ float Ks[NTOK * HDIM];
    __shared__ float Vs[NTOK * HDIM];

    const int wh = blockIdx.x;
    const int tid = threadIdx.x;
    const float* kp = g_k + wh * (NTOK * HDIM);
    const float* vp = g_v + wh * (NTOK * HDIM);

    for (int i = tid; i < NTOK * HDIM / 4; i += 160) {
        ((float4*)Ks)[i] = ((const float4*)kp)[i];
        ((float4*)Vs)[i] = ((const float4*)vp)[i];
    }
    __syncthreads();

    if (tid < NTOK) {
        float q[HDIM];
        const float* qp = g_q + wh * (NTOK * HDIM) + tid * HDIM;
        #pragma unroll
        for (int d4 = 0; d4 < HDIM / 4; ++d4) {
            float4 v = ((const float4*)qp)[d4];
            q[d4 * 4 + 0] = v.x; q[d4 * 4 + 1] = v.y;
            q[d4 * 4 + 2] = v.z; q[d4 * 4 + 3] = v.w;
        }

        float acc[HDIM] = {};
        float sum = 0.f;
        const float scale = 0.1767766952966369f;   // 32^-0.5

        for (int j = 0; j < NTOK; ++j) {
            const float4* kr = (const float4*)&Ks[j * HDIM];
            float s = 0.f;
            #pragma unroll
            for (int d4 = 0; d4 < HDIM / 4; ++d4) {
                float4 kv = kr[d4];
                s = fmaf(q[d4 * 4 + 0], kv.x, s);
                s = fmaf(q[d4 * 4 + 1], kv.y, s);
                s = fmaf(q[d4 * 4 + 2], kv.z, s);
                s = fmaf(q[d4 * 4 + 3], kv.w, s);
            }
            const float e = __expf(s * scale);
            sum += e;
            const float4* vr = (const float4*)&Vs[j * HDIM];
            #pragma unroll
            for (int d4 = 0; d4 < HDIM / 4; ++d4) {
                float4 vv = vr[d4];
                acc[d4 * 4 + 0] = fmaf(e, vv.x, acc[d4 * 4 + 0]);
                acc[d4 * 4 + 1] = fmaf(e, vv.y, acc[d4 * 4 + 1]);
                acc[d4 * 4 + 2] = fmaf(e, vv.z, acc[d4 * 4 + 2]);
                acc[d4 * 4 + 3] = fmaf(e, vv.w, acc[d4 * 4 + 3]);
            }
        }

        const float inv = 1.f / sum;
        const int win = wh >> 4, head = wh & 15;
        const int base = (win * NTOK + tid) * DIM + head * HDIM;
        #pragma unroll
        for (int p = 0; p < 4; ++p) {
            __align__(16) __half hs[8];
            #pragma unroll
            for (int j = 0; j < 8; ++j)
                hs[j] = __float2half(acc[p * 8 + j] * inv);
            *(uint4*)&g_ao[base + p * 8] = *(uint4*)hs;
        }
    }
}

// ---------------------------------------------------------------------------
// Kernel: proj GEMM. epilogue: +bias, window_reverse scatter -> out fp32
// ---------------------------------------------------------------------------
__global__ __launch_bounds__(256, 2)
void proj_hgemm_kernel(const float* __restrict__ bias, float* __restrict__ out)
{
    float acc[2][8][4] = {};
    const int m0 = blockIdx.y * 128, n0 = blockIdx.x * 128;
    hgemm_tile(g_ao, g_wp, m0, n0, acc);

    const int tid = threadIdx.x, lane = tid & 31, wid = tid >> 5;
    const int g = lane >> 2, t = lane & 3;
    const int wm = (wid & 3) * 32, wn = (wid >> 2) * 64;

    #pragma unroll
    for (int i = 0; i < 2; ++i) {
        #pragma unroll
        for (int h = 0; h < 2; ++h) {
            const int m = m0 + wm + i * 16 + h * 8 + g;
            const int win = m / NTOK, tok = m % NTOK;
            const int b = win >> 4, yw = (win >> 2) & 3, xw = win & 3;
            const int y = yw * 12 + tok / 12;
            const int x = xw * 12 + tok % 12;
            float* orow = out + ((b * 2304 + y * 48 + x) << 9);
            #pragma unroll
            for (int j = 0; j < 8; ++j) {
                const int n = n0 + wn + j * 8 + 2 * t;
                float2 v;
                v.x = acc[i][j][h * 2 + 0] + bias[n + 0];
                v.y = acc[i][j][h * 2 + 1] + bias[n + 1];
                *(float2*)&orow[n] = v;
            }
        }
    }
}

// ---------------------------------------------------------------------------
extern "C" void kernel_launch(void* const* d_in, const int* in_sizes, int n_in,
                              void* d_out, int out_size)
{
    const float* hidden = (const float*)d_in[0];
    const float* qkv_w  = (const float*)d_in[1];
    const float* qkv_b  = (const float*)d_in[2];
    const float* proj_w = (const float*)d_in[3];
    const float* proj_b = (const float*)d_in[4];
    float* out = (float*)d_out;

    convert_x_kernel<<<MTOT * 64 / 256, 256>>>(hidden);
    convert_w_kernel<<<dim3(NQKV / 32, DIM / 32), dim3(32, 8)>>>(qkv_w, 0);
    convert_w_kernel<<<dim3(DIM / 32, DIM / 32), dim3(32, 8)>>>(proj_w, 1);

    qkv_hgemm_kernel<<<dim3(NQKV / 128, MTOT / 128), 256>>>(qkv_b);

    attn_kernel<<<NWIN * NHEAD, 160>>>();

    proj_hgemm_kernel<<<dim3(DIM / 128, MTOT / 128), 256>>>(proj_b, out);
}

// round 7
// speedup vs baseline: 5.3434x; 2.0680x over previous
#include <cuda_runtime.h>
#include <cuda_fp16.h>
#include <cstdint>

// ---------------------------------------------------------------------------
// Florence2 window attention — all three matmul stages on mma.sync (fp16/fp32).
// hidden (8,48,48,512), qkv_w (512,1536), proj_w (512,512)
// WINDOW=12 -> 128 windows x 144 tokens, 16 heads x 32 dim.
// ---------------------------------------------------------------------------

#define NWIN   128
#define NTOK   144
#define DIM    512
#define NHEAD  16
#define HDIM   32
#define MTOT   (NWIN * NTOK)     // 18432
#define NQKV   1536

#define SROW   72                // hgemm smem row stride in halves (144B)

// ---------------- scratch (device globals; device-code refs only) ----------
__device__ __align__(16) __half g_x  [MTOT * DIM];             // X [m][k]
__device__ __align__(16) __half g_wq [NQKV * DIM];             // qkv_w^T [n][k]
__device__ __align__(16) __half g_wp [DIM * DIM];              // proj_w^T [n][k]
__device__ __align__(16) __half g_qh [NWIN * NHEAD * NTOK * HDIM];  // Q*scale [wh][tok][d]
__device__ __align__(16) __half g_kh [NWIN * NHEAD * NTOK * HDIM];  // K [wh][tok][d]
__device__ __align__(16) __half g_vT [NWIN * NHEAD * HDIM * NTOK];  // V^T [wh][d][tok]
__device__ __align__(16) __half g_ao [MTOT * DIM];             // attn out [m][k]

// ---------------- mma.sync helper ------------------------------------------
__device__ __forceinline__ void mma16816(float* d, const uint32_t* a,
                                         uint32_t b0, uint32_t b1) {
    asm volatile("mma.sync.aligned.m16n8k16.row.col.f32.f16.f16.f32 "
        "{%0,%1,%2,%3}, {%4,%5,%6,%7}, {%8,%9}, {%0,%1,%2,%3};"
        : "+f"(d[0]), "+f"(d[1]), "+f"(d[2]), "+f"(d[3])
        : "r"(a[0]), "r"(a[1]), "r"(a[2]), "r"(a[3]), "r"(b0), "r"(b1));
}

__device__ __forceinline__ int hidden_row_off(int m) {
    int win = m / NTOK, t = m % NTOK;
    int b = win >> 4, yw = (win >> 2) & 3, xw = win & 3;
    int y = yw * 12 + t / 12;
    int x = xw * 12 + t % 12;
    return ((b * 48 + y) * 48 + x) * DIM;
}

// ---------------------------------------------------------------------------
// conversion kernels (fp32 -> fp16)
// ---------------------------------------------------------------------------
__global__ void convert_x_kernel(const float* __restrict__ hidden) {
    int idx = blockIdx.x * 256 + threadIdx.x;       // m*64 + seg
    int m = idx >> 6, seg = idx & 63;
    const float* src = hidden + hidden_row_off(m) + seg * 8;
    float4 f0 = *(const float4*)src;
    float4 f1 = *(const float4*)(src + 4);
    __align__(16) __half h[8];
    h[0] = __float2half(f0.x); h[1] = __float2half(f0.y);
    h[2] = __float2half(f0.z); h[3] = __float2half(f0.w);
    h[4] = __float2half(f1.x); h[5] = __float2half(f1.y);
    h[6] = __float2half(f1.z); h[7] = __float2half(f1.w);
    *(uint4*)&g_x[m * DIM + seg * 8] = *(uint4*)h;
}

// transpose W [K=512][N] -> [n][512]; sel 0 -> g_wq (N=1536), 1 -> g_wp (N=512)
__global__ void convert_w_kernel(const float* __restrict__ W, int sel) {
    __shared__ float t[32][33];
    const int N = sel ? DIM : NQKV;
    __half* __restrict__ outT = sel ? g_wp : g_wq;
    int tx = threadIdx.x, ty = threadIdx.y;
    int n0 = blockIdx.x * 32, k0 = blockIdx.y * 32;
    #pragma unroll
    for (int j = 0; j < 4; ++j)
        t[ty + 8 * j][tx] = W[(k0 + ty + 8 * j) * N + n0 + tx];
    __syncthreads();
    #pragma unroll
    for (int j = 0; j < 4; ++j)
        outT[(n0 + ty + 8 * j) * DIM + k0 + tx] = __float2half(t[tx][ty + 8 * j]);
}

// ---------------------------------------------------------------------------
// HGEMM mainloop (proven): 128x128 tile, K in 8 chunks of 64, LDG->STS staged.
// ---------------------------------------------------------------------------
__device__ __forceinline__ void hgemm_tile(
    const __half* __restrict__ A, const __half* __restrict__ B,
    int m0, int n0, float acc[2][8][4])
{
    __shared__ __align__(16) __half sA[128 * SROW];
    __shared__ __align__(16) __half sB[128 * SROW];

    const int tid = threadIdx.x;
    const int lane = tid & 31, wid = tid >> 5;
    const int g = lane >> 2, t = lane & 3;
    const int wm = (wid & 3) * 32, wn = (wid >> 2) * 64;

    int rowv[4], uv[4];
    #pragma unroll
    for (int i = 0; i < 4; ++i) {
        rowv[i] = 32 * i + (tid >> 3);
        uv[i]   = tid & 7;
    }

    uint4 rga[4], rgb[4];
    #pragma unroll
    for (int i = 0; i < 4; ++i) {
        rga[i] = *(const uint4*)(A + (m0 + rowv[i]) * DIM + uv[i] * 8);
        rgb[i] = *(const uint4*)(B + (n0 + rowv[i]) * DIM + uv[i] * 8);
    }

    #pragma unroll 1
    for (int ch = 0; ch < 8; ++ch) {
        #pragma unroll
        for (int i = 0; i < 4; ++i) {
            *(uint4*)&sA[rowv[i] * SROW + uv[i] * 8] = rga[i];
            *(uint4*)&sB[rowv[i] * SROW + uv[i] * 8] = rgb[i];
        }
        __syncthreads();

        if (ch < 7) {
            const int ko = (ch + 1) * 64;
            #pragma unroll
            for (int i = 0; i < 4; ++i) {
                rga[i] = *(const uint4*)(A + (m0 + rowv[i]) * DIM + ko + uv[i] * 8);
                rgb[i] = *(const uint4*)(B + (n0 + rowv[i]) * DIM + ko + uv[i] * 8);
            }
        }

        #pragma unroll
        for (int s = 0; s < 4; ++s) {
            const int k0 = s * 16 + 2 * t;
            uint32_t a[2][4];
            #pragma unroll
            for (int i = 0; i < 2; ++i) {
                const int r = wm + i * 16 + g;
                a[i][0] = *(const uint32_t*)&sA[ r      * SROW + k0    ];
                a[i][1] = *(const uint32_t*)&sA[(r + 8) * SROW + k0    ];
                a[i][2] = *(const uint32_t*)&sA[ r      * SROW + k0 + 8];
                a[i][3] = *(const uint32_t*)&sA[(r + 8) * SROW + k0 + 8];
            }
            #pragma unroll
            for (int j = 0; j < 8; ++j) {
                const int rn = wn + j * 8 + g;
                uint32_t b0 = *(const uint32_t*)&sB[rn * SROW + k0    ];
                uint32_t b1 = *(const uint32_t*)&sB[rn * SROW + k0 + 8];
                mma16816(acc[0][j], a[0], b0, b1);
                mma16816(acc[1][j], a[1], b0, b1);
            }
        }
        __syncthreads();
    }
}

// ---------------------------------------------------------------------------
// Kernel: QKV GEMM. epilogue: +bias -> fp16 Q (pre-scaled), K, V^T
// ---------------------------------------------------------------------------
__global__ __launch_bounds__(256, 2)
void qkv_hgemm_kernel(const float* __restrict__ bias)
{
    float acc[2][8][4] = {};
    const int m0 = blockIdx.y * 128, n0 = blockIdx.x * 128;
    hgemm_tile(g_x, g_wq, m0, n0, acc);

    const int tid = threadIdx.x, lane = tid & 31, wid = tid >> 5;
    const int g = lane >> 2, t = lane & 3;
    const int wm = (wid & 3) * 32, wn = (wid >> 2) * 64;
    const float scale = 0.1767766952966369f;   // 32^-0.5

    #pragma unroll
    for (int i = 0; i < 2; ++i) {
        #pragma unroll
        for (int h = 0; h < 2; ++h) {
            const int m = m0 + wm + i * 16 + h * 8 + g;
            const int win = m / NTOK, tok = m % NTOK;
            #pragma unroll
            for (int j = 0; j < 8; ++j) {
                const int n = n0 + wn + j * 8 + 2 * t;
                const int sel = n >> 9, head = (n >> 5) & 15, d = n & 31;
                const int wh = (win << 4) + head;
                float vx = acc[i][j][h * 2 + 0] + bias[n + 0];
                float vy = acc[i][j][h * 2 + 1] + bias[n + 1];
                if (sel == 0) {
                    *(__half2*)&g_qh[(wh * NTOK + tok) * HDIM + d] =
                        __floats2half2_rn(vx * scale, vy * scale);
                } else if (sel == 1) {
                    *(__half2*)&g_kh[(wh * NTOK + tok) * HDIM + d] =
                        __floats2half2_rn(vx, vy);
                } else {
                    g_vT[(wh * HDIM + d    ) * NTOK + tok] = __float2half(vx);
                    g_vT[(wh * HDIM + d + 1) * NTOK + tok] = __float2half(vy);
                }
            }
        }
    }
}

// ---------------------------------------------------------------------------
// Kernel: tensor-core attention. 1 block per (win,head), 96 thr = 3 warps,
// each warp 3 Q-tiles of 16 rows. Unnormalized exp -> P fp16 fragments in
// registers -> PV mma -> scale by 1/rowsum.
// ---------------------------------------------------------------------------
#define QROW 40     // sQ/sK row stride (halves): conflict-free
#define VROW 152    // sVT row stride (halves): 16B-aligned segs + conflict-free

__global__ __launch_bounds__(96)
void attn_mma_kernel()
{
    __shared__ __align__(16) __half sQ[NTOK * QROW];   // 11520 B
    __shared__ __align__(16) __half sK[NTOK * QROW];   // 11520 B
    __shared__ __align__(16) __half sVT[HDIM * VROW];  //  9728 B

    const int wh = blockIdx.x;
    const int tid = threadIdx.x, lane = tid & 31, wid = tid >> 5;
    const int g = lane >> 2, t = lane & 3;

    const __half* qp = g_qh + wh * (NTOK * HDIM);
    const __half* kp = g_kh + wh * (NTOK * HDIM);
    const __half* vp = g_vT + wh * (HDIM * NTOK);

    for (int seg = tid; seg < 576; seg += 96) {
        int row = seg >> 2, sub = seg & 3;            // Q/K: 144 rows x 4 segs
        *(uint4*)&sQ[row * QROW + sub * 8] = *(const uint4*)(qp + row * HDIM + sub * 8);
        *(uint4*)&sK[row * QROW + sub * 8] = *(const uint4*)(kp + row * HDIM + sub * 8);
        int vrow = seg / 18, vsub = seg - vrow * 18;  // VT: 32 rows x 18 segs
        *(uint4*)&sVT[vrow * VROW + vsub * 8] = *(const uint4*)(vp + vrow * NTOK + vsub * 8);
    }
    __syncthreads();

    const int win = wh >> 4, head = wh & 15;

    #pragma unroll 1
    for (int ti = 0; ti < 3; ++ti) {
        const int tile = wid * 3 + ti;
        const int r = tile * 16 + g;

        // Q A-fragments for both d-ksteps
        uint32_t qa[2][4];
        #pragma unroll
        for (int s = 0; s < 2; ++s) {
            const int c = s * 16 + 2 * t;
            qa[s][0] = *(const uint32_t*)&sQ[ r      * QROW + c    ];
            qa[s][1] = *(const uint32_t*)&sQ[(r + 8) * QROW + c    ];
            qa[s][2] = *(const uint32_t*)&sQ[ r      * QROW + c + 8];
            qa[s][3] = *(const uint32_t*)&sQ[(r + 8) * QROW + c + 8];
        }

        // QK^T -> exp -> packed P fragments (per-tile, scores die immediately)
        uint32_t eh[18][2];
        float sum0 = 0.f, sum1 = 0.f;
        #pragma unroll
        for (int j = 0; j < 18; ++j) {
            float sc[4] = {};
            const int rn = 8 * j + g;
            #pragma unroll
            for (int s = 0; s < 2; ++s) {
                const int c = s * 16 + 2 * t;
                uint32_t b0 = *(const uint32_t*)&sK[rn * QROW + c    ];
                uint32_t b1 = *(const uint32_t*)&sK[rn * QROW + c + 8];
                mma16816(sc, qa[s], b0, b1);
            }
            float e0 = __expf(sc[0]), e1 = __expf(sc[1]);
            float e2 = __expf(sc[2]), e3 = __expf(sc[3]);
            sum0 += e0 + e1; sum1 += e2 + e3;
            __half2 p01 = __floats2half2_rn(e0, e1);
            __half2 p23 = __floats2half2_rn(e2, e3);
            eh[j][0] = *(uint32_t*)&p01;
            eh[j][1] = *(uint32_t*)&p23;
        }
        sum0 += __shfl_xor_sync(0xffffffffu, sum0, 1);
        sum0 += __shfl_xor_sync(0xffffffffu, sum0, 2);
        sum1 += __shfl_xor_sync(0xffffffffu, sum1, 1);
        sum1 += __shfl_xor_sync(0xffffffffu, sum1, 2);

        // P @ V  (B = V^T rows = d)
        float acc[4][4] = {};
        #pragma unroll
        for (int kk = 0; kk < 9; ++kk) {
            uint32_t a[4] = {eh[2 * kk][0], eh[2 * kk][1],
                             eh[2 * kk + 1][0], eh[2 * kk + 1][1]};
            #pragma unroll
            for (int nd = 0; nd < 4; ++nd) {
                const int rn = 8 * nd + g;
                uint32_t b0 = *(const uint32_t*)&sVT[rn * VROW + kk * 16 + 2 * t    ];
                uint32_t b1 = *(const uint32_t*)&sVT[rn * VROW + kk * 16 + 2 * t + 8];
                mma16816(acc[nd], a, b0, b1);
            }
        }

        const float inv0 = 1.f / sum0, inv1 = 1.f / sum1;
        __half* o0 = g_ao + (win * NTOK + r) * DIM + head * HDIM;
        __half* o1 = o0 + 8 * DIM;
        #pragma unroll
        for (int nd = 0; nd < 4; ++nd) {
            const int d = 8 * nd + 2 * t;
            *(__half2*)&o0[d] = __floats2half2_rn(acc[nd][0] * inv0, acc[nd][1] * inv0);
            *(__half2*)&o1[d] = __floats2half2_rn(acc[nd][2] * inv1, acc[nd][3] * inv1);
        }
    }
}

// ---------------------------------------------------------------------------
// Kernel: proj GEMM. epilogue: +bias, window_reverse scatter -> out fp32
// ---------------------------------------------------------------------------
__global__ __launch_bounds__(256, 2)
void proj_hgemm_kernel(const float* __restrict__ bias, float* __restrict__ out)
{
    float acc[2][8][4] = {};
    const int m0 = blockIdx.y * 128, n0 = blockIdx.x * 128;
    hgemm_tile(g_ao, g_wp, m0, n0, acc);

    const int tid = threadIdx.x, lane = tid & 31, wid = tid >> 5;
    const int g = lane >> 2, t = lane & 3;
    const int wm = (wid & 3) * 32, wn = (wid >> 2) * 64;

    #pragma unroll
    for (int i = 0; i < 2; ++i) {
        #pragma unroll
        for (int h = 0; h < 2; ++h) {
            const int m = m0 + wm + i * 16 + h * 8 + g;
            const int win = m / NTOK, tok = m % NTOK;
            const int b = win >> 4, yw = (win >> 2) & 3, xw = win & 3;
            const int y = yw * 12 + tok / 12;
            const int x = xw * 12 + tok % 12;
            float* orow = out + ((b * 2304 + y * 48 + x) << 9);
            #pragma unroll
            for (int j = 0; j < 8; ++j) {
                const int n = n0 + wn + j * 8 + 2 * t;
                float2 v;
                v.x = acc[i][j][h * 2 + 0] + bias[n + 0];
                v.y = acc[i][j][h * 2 + 1] + bias[n + 1];
                *(float2*)&orow[n] = v;
            }
        }
    }
}

// ---------------------------------------------------------------------------
extern "C" void kernel_launch(void* const* d_in, const int* in_sizes, int n_in,
                              void* d_out, int out_size)
{
    const float* hidden = (const float*)d_in[0];
    const float* qkv_w  = (const float*)d_in[1];
    const float* qkv_b  = (const float*)d_in[2];
    const float* proj_w = (const float*)d_in[3];
    const float* proj_b = (const float*)d_in[4];
    float* out = (float*)d_out;

    convert_x_kernel<<<MTOT * 64 / 256, 256>>>(hidden);
    convert_w_kernel<<<dim3(NQKV / 32, DIM / 32), dim3(32, 8)>>>(qkv_w, 0);
    convert_w_kernel<<<dim3(DIM / 32, DIM / 32), dim3(32, 8)>>>(proj_w, 1);

    qkv_hgemm_kernel<<<dim3(NQKV / 128, MTOT / 128), 256>>>(qkv_b);

    attn_mma_kernel<<<NWIN * NHEAD, 96>>>();

    proj_hgemm_kernel<<<dim3(DIM / 128, MTOT / 128), 256>>>(proj_b, out);
}

// round 8
// speedup vs baseline: 6.0416x; 1.1306x over previous
#include <cuda_runtime.h>
#include <cuda_fp16.h>
#include <cstdint>

// ---------------------------------------------------------------------------
// Florence2 window attention — all three matmul stages on mma.sync (fp16/fp32).
// R8: hgemm mainloop rebuilt with ldmatrix.x4 + cp.async double buffering.
// hidden (8,48,48,512), qkv_w (512,1536), proj_w (512,512)
// WINDOW=12 -> 128 windows x 144 tokens, 16 heads x 32 dim.
// ---------------------------------------------------------------------------

#define NWIN   128
#define NTOK   144
#define DIM    512
#define NHEAD  16
#define HDIM   32
#define MTOT   (NWIN * NTOK)     // 18432
#define NQKV   1536

#define SROW   72                // hgemm smem row stride in halves (144B, 9x16B)

// ---------------- scratch (device globals; device-code refs only) ----------
__device__ __align__(16) __half g_x  [MTOT * DIM];             // X [m][k]
__device__ __align__(16) __half g_wq [NQKV * DIM];             // qkv_w^T [n][k]
__device__ __align__(16) __half g_wp [DIM * DIM];              // proj_w^T [n][k]
__device__ __align__(16) __half g_qh [NWIN * NHEAD * NTOK * HDIM];  // Q*scale
__device__ __align__(16) __half g_kh [NWIN * NHEAD * NTOK * HDIM];  // K
__device__ __align__(16) __half g_vT [NWIN * NHEAD * HDIM * NTOK];  // V^T
__device__ __align__(16) __half g_ao [MTOT * DIM];             // attn out [m][k]

// ---------------- PTX helpers (sm_80-level, family-safe) -------------------
__device__ __forceinline__ uint32_t smem_u32(const void* p) {
    uint32_t a;
    asm("{ .reg .u64 t; cvta.to.shared.u64 t, %1; cvt.u32.u64 %0, t; }" : "=r"(a) : "l"(p));
    return a;
}
__device__ __forceinline__ void cp_async16(uint32_t s, const void* g) {
    asm volatile("cp.async.cg.shared.global [%0], [%1], 16;" :: "r"(s), "l"(g));
}
__device__ __forceinline__ void cp_commit() { asm volatile("cp.async.commit_group;"); }
__device__ __forceinline__ void cp_wait1()  { asm volatile("cp.async.wait_group 1;"); }
__device__ __forceinline__ void cp_wait0()  { asm volatile("cp.async.wait_group 0;"); }

__device__ __forceinline__ void ldsm_x4(uint32_t* r, uint32_t addr) {
    asm volatile("ldmatrix.sync.aligned.m8n8.x4.shared.b16 {%0,%1,%2,%3}, [%4];"
        : "=r"(r[0]), "=r"(r[1]), "=r"(r[2]), "=r"(r[3]) : "r"(addr));
}
__device__ __forceinline__ void mma16816(float* d, const uint32_t* a,
                                         uint32_t b0, uint32_t b1) {
    asm volatile("mma.sync.aligned.m16n8k16.row.col.f32.f16.f16.f32 "
        "{%0,%1,%2,%3}, {%4,%5,%6,%7}, {%8,%9}, {%0,%1,%2,%3};"
        : "+f"(d[0]), "+f"(d[1]), "+f"(d[2]), "+f"(d[3])
        : "r"(a[0]), "r"(a[1]), "r"(a[2]), "r"(a[3]), "r"(b0), "r"(b1));
}

__device__ __forceinline__ int hidden_row_off(int m) {
    int win = m / NTOK, t = m % NTOK;
    int b = win >> 4, yw = (win >> 2) & 3, xw = win & 3;
    int y = yw * 12 + t / 12;
    int x = xw * 12 + t % 12;
    return ((b * 48 + y) * 48 + x) * DIM;
}

// ---------------------------------------------------------------------------
// conversion kernels (fp32 -> fp16)
// ---------------------------------------------------------------------------
__global__ void convert_x_kernel(const float* __restrict__ hidden) {
    int idx = blockIdx.x * 256 + threadIdx.x;       // m*64 + seg
    int m = idx >> 6, seg = idx & 63;
    const float* src = hidden + hidden_row_off(m) + seg * 8;
    float4 f0 = *(const float4*)src;
    float4 f1 = *(const float4*)(src + 4);
    __align__(16) __half h[8];
    h[0] = __float2half(f0.x); h[1] = __float2half(f0.y);
    h[2] = __float2half(f0.z); h[3] = __float2half(f0.w);
    h[4] = __float2half(f1.x); h[5] = __float2half(f1.y);
    h[6] = __float2half(f1.z); h[7] = __float2half(f1.w);
    *(uint4*)&g_x[m * DIM + seg * 8] = *(uint4*)h;
}

// transpose W [K=512][N] -> [n][512]; sel 0 -> g_wq (N=1536), 1 -> g_wp (N=512)
__global__ void convert_w_kernel(const float* __restrict__ W, int sel) {
    __shared__ float t[32][33];
    const int N = sel ? DIM : NQKV;
    __half* __restrict__ outT = sel ? g_wp : g_wq;
    int tx = threadIdx.x, ty = threadIdx.y;
    int n0 = blockIdx.x * 32, k0 = blockIdx.y * 32;
    #pragma unroll
    for (int j = 0; j < 4; ++j)
        t[ty + 8 * j][tx] = W[(k0 + ty + 8 * j) * N + n0 + tx];
    __syncthreads();
    #pragma unroll
    for (int j = 0; j < 4; ++j)
        outT[(n0 + ty + 8 * j) * DIM + k0 + tx] = __float2half(t[tx][ty + 8 * j]);
}

// ---------------------------------------------------------------------------
// HGEMM mainloop: 128x128 tile, K=512 in 8 chunks of 64.
// cp.async double-buffered smem; ldmatrix.x4 fragment loads.
// 8 warps: warp tile 32(M) x 64(N). A [m][k], B [n][k] fp16.
// ---------------------------------------------------------------------------
#define BUFH (128 * SROW)        // halves per buffer (per operand)

__device__ __forceinline__ void hgemm_tile(
    const __half* __restrict__ A, const __half* __restrict__ B,
    int m0, int n0, float acc[2][8][4])
{
    __shared__ __align__(16) __half sA[2][BUFH];
    __shared__ __align__(16) __half sB[2][BUFH];

    const int tid = threadIdx.x;
    const int lane = tid & 31, wid = tid >> 5;
    const int wm = (wid & 3) * 32, wn = (wid >> 2) * 64;

    const uint32_t aBase = smem_u32(&sA[0][0]);
    const uint32_t bBase = smem_u32(&sB[0][0]);

    // ---- cp.async staging coords: 4 x 16B segments per operand per thread
    int rowv[4];
    const int uvb = (tid & 7) * 16;          // byte offset of 16B unit in row
    #pragma unroll
    for (int i = 0; i < 4; ++i) rowv[i] = 32 * i + (tid >> 3);

    uint32_t stA[4], stB[4];
    const __half* gA[4];
    const __half* gB[4];
    #pragma unroll
    for (int i = 0; i < 4; ++i) {
        stA[i] = aBase + rowv[i] * (SROW * 2) + uvb;
        stB[i] = bBase + rowv[i] * (SROW * 2) + uvb;
        gA[i] = A + (m0 + rowv[i]) * DIM + (tid & 7) * 8;
        gB[i] = B + (n0 + rowv[i]) * DIM + (tid & 7) * 8;
    }

    // ---- ldmatrix lane addressing (byte offsets)
    const int la = lane & 7;
    const int arow = wm + la + ((lane & 8) ? 8 : 0);
    const int acol = (lane & 16) ? 8 : 0;            // halves
    const int brow = wn + la + ((lane & 16) ? 8 : 0);
    const int bcol = (lane & 8) ? 8 : 0;

    const uint32_t aFrag0 = aBase + arow * (SROW * 2) + acol * 2;
    const uint32_t bFrag0 = bBase + brow * (SROW * 2) + bcol * 2;

    // prologue: chunk 0 -> buf 0
    #pragma unroll
    for (int i = 0; i < 4; ++i) {
        cp_async16(stA[i], gA[i]);
        cp_async16(stB[i], gB[i]);
    }
    cp_commit();

    #pragma unroll 1
    for (int ch = 0; ch < 8; ++ch) {
        if (ch < 7) {
            const uint32_t bo = ((ch + 1) & 1) * (BUFH * 2);
            const int ko = (ch + 1) * 64;
            #pragma unroll
            for (int i = 0; i < 4; ++i) {
                cp_async16(stA[i] + bo, gA[i] + ko);
                cp_async16(stB[i] + bo, gB[i] + ko);
            }
            cp_commit();
            cp_wait1();
        } else {
            cp_wait0();
        }
        __syncthreads();

        const uint32_t bo = (ch & 1) * (BUFH * 2);
        #pragma unroll
        for (int s = 0; s < 4; ++s) {
            const uint32_t kb = s * 32;              // 16 halves = 32 bytes
            uint32_t a[2][4];
            ldsm_x4(a[0], aFrag0 + bo + kb);
            ldsm_x4(a[1], aFrag0 + bo + kb + 16 * (SROW * 2));
            #pragma unroll
            for (int j2 = 0; j2 < 4; ++j2) {
                uint32_t rb[4];
                ldsm_x4(rb, bFrag0 + bo + kb + j2 * 16 * (SROW * 2));
                mma16816(acc[0][2 * j2 + 0], a[0], rb[0], rb[1]);
                mma16816(acc[0][2 * j2 + 1], a[0], rb[2], rb[3]);
                mma16816(acc[1][2 * j2 + 0], a[1], rb[0], rb[1]);
                mma16816(acc[1][2 * j2 + 1], a[1], rb[2], rb[3]);
            }
        }
        __syncthreads();
    }
}

// ---------------------------------------------------------------------------
// Kernel: QKV GEMM. epilogue: +bias -> fp16 Q (pre-scaled), K, V^T
// ---------------------------------------------------------------------------
__global__ __launch_bounds__(256, 2)
void qkv_hgemm_kernel(const float* __restrict__ bias)
{
    float acc[2][8][4] = {};
    const int m0 = blockIdx.y * 128, n0 = blockIdx.x * 128;
    hgemm_tile(g_x, g_wq, m0, n0, acc);

    const int tid = threadIdx.x, lane = tid & 31, wid = tid >> 5;
    const int g = lane >> 2, t = lane & 3;
    const int wm = (wid & 3) * 32, wn = (wid >> 2) * 64;
    const float scale = 0.1767766952966369f;   // 32^-0.5

    #pragma unroll
    for (int i = 0; i < 2; ++i) {
        #pragma unroll
        for (int h = 0; h < 2; ++h) {
            const int m = m0 + wm + i * 16 + h * 8 + g;
            const int win = m / NTOK, tok = m % NTOK;
            #pragma unroll
            for (int j = 0; j < 8; ++j) {
                const int n = n0 + wn + j * 8 + 2 * t;
                const int sel = n >> 9, head = (n >> 5) & 15, d = n & 31;
                const int wh = (win << 4) + head;
                float vx = acc[i][j][h * 2 + 0] + bias[n + 0];
                float vy = acc[i][j][h * 2 + 1] + bias[n + 1];
                if (sel == 0) {
                    *(__half2*)&g_qh[(wh * NTOK + tok) * HDIM + d] =
                        __floats2half2_rn(vx * scale, vy * scale);
                } else if (sel == 1) {
                    *(__half2*)&g_kh[(wh * NTOK + tok) * HDIM + d] =
                        __floats2half2_rn(vx, vy);
                } else {
                    g_vT[(wh * HDIM + d    ) * NTOK + tok] = __float2half(vx);
                    g_vT[(wh * HDIM + d + 1) * NTOK + tok] = __float2half(vy);
                }
            }
        }
    }
}

// ---------------------------------------------------------------------------
// Kernel: tensor-core attention (proven R7). 1 block per (win,head), 96 thr.
// ---------------------------------------------------------------------------
#define QROW 40     // sQ/sK row stride (halves)
#define VROW 152    // sVT row stride (halves)

__global__ __launch_bounds__(96)
void attn_mma_kernel()
{
    __shared__ __align__(16) __half sQ[NTOK * QROW];
    __shared__ __align__(16) __half sK[NTOK * QROW];
    __shared__ __align__(16) __half sVT[HDIM * VROW];

    const int wh = blockIdx.x;
    const int tid = threadIdx.x, lane = tid & 31, wid = tid >> 5;
    const int g = lane >> 2, t = lane & 3;

    const __half* qp = g_qh + wh * (NTOK * HDIM);
    const __half* kp = g_kh + wh * (NTOK * HDIM);
    const __half* vp = g_vT + wh * (HDIM * NTOK);

    for (int seg = tid; seg < 576; seg += 96) {
        int row = seg >> 2, sub = seg & 3;
        *(uint4*)&sQ[row * QROW + sub * 8] = *(const uint4*)(qp + row * HDIM + sub * 8);
        *(uint4*)&sK[row * QROW + sub * 8] = *(const uint4*)(kp + row * HDIM + sub * 8);
        int vrow = seg / 18, vsub = seg - vrow * 18;
        *(uint4*)&sVT[vrow * VROW + vsub * 8] = *(const uint4*)(vp + vrow * NTOK + vsub * 8);
    }
    __syncthreads();

    const int win = wh >> 4, head = wh & 15;

    #pragma unroll 1
    for (int ti = 0; ti < 3; ++ti) {
        const int tile = wid * 3 + ti;
        const int r = tile * 16 + g;

        uint32_t qa[2][4];
        #pragma unroll
        for (int s = 0; s < 2; ++s) {
            const int c = s * 16 + 2 * t;
            qa[s][0] = *(const uint32_t*)&sQ[ r      * QROW + c    ];
            qa[s][1] = *(const uint32_t*)&sQ[(r + 8) * QROW + c    ];
            qa[s][2] = *(const uint32_t*)&sQ[ r      * QROW + c + 8];
            qa[s][3] = *(const uint32_t*)&sQ[(r + 8) * QROW + c + 8];
        }

        uint32_t eh[18][2];
        float sum0 = 0.f, sum1 = 0.f;
        #pragma unroll
        for (int j = 0; j < 18; ++j) {
            float sc[4] = {};
            const int rn = 8 * j + g;
            #pragma unroll
            for (int s = 0; s < 2; ++s) {
                const int c = s * 16 + 2 * t;
                uint32_t b0 = *(const uint32_t*)&sK[rn * QROW + c    ];
                uint32_t b1 = *(const uint32_t*)&sK[rn * QROW + c + 8];
                mma16816(sc, qa[s], b0, b1);
            }
            float e0 = __expf(sc[0]), e1 = __expf(sc[1]);
            float e2 = __expf(sc[2]), e3 = __expf(sc[3]);
            sum0 += e0 + e1; sum1 += e2 + e3;
            __half2 p01 = __floats2half2_rn(e0, e1);
            __half2 p23 = __floats2half2_rn(e2, e3);
            eh[j][0] = *(uint32_t*)&p01;
            eh[j][1] = *(uint32_t*)&p23;
        }
        sum0 += __shfl_xor_sync(0xffffffffu, sum0, 1);
        sum0 += __shfl_xor_sync(0xffffffffu, sum0, 2);
        sum1 += __shfl_xor_sync(0xffffffffu, sum1, 1);
        sum1 += __shfl_xor_sync(0xffffffffu, sum1, 2);

        float acc[4][4] = {};
        #pragma unroll
        for (int kk = 0; kk < 9; ++kk) {
            uint32_t a[4] = {eh[2 * kk][0], eh[2 * kk][1],
                             eh[2 * kk + 1][0], eh[2 * kk + 1][1]};
            #pragma unroll
            for (int nd = 0; nd < 4; ++nd) {
                const int rn = 8 * nd + g;
                uint32_t b0 = *(const uint32_t*)&sVT[rn * VROW + kk * 16 + 2 * t    ];
                uint32_t b1 = *(const uint32_t*)&sVT[rn * VROW + kk * 16 + 2 * t + 8];
                mma16816(acc[nd], a, b0, b1);
            }
        }

        const float inv0 = 1.f / sum0, inv1 = 1.f / sum1;
        __half* o0 = g_ao + (win * NTOK + r) * DIM + head * HDIM;
        __half* o1 = o0 + 8 * DIM;
        #pragma unroll
        for (int nd = 0; nd < 4; ++nd) {
            const int d = 8 * nd + 2 * t;
            *(__half2*)&o0[d] = __floats2half2_rn(acc[nd][0] * inv0, acc[nd][1] * inv0);
            *(__half2*)&o1[d] = __floats2half2_rn(acc[nd][2] * inv1, acc[nd][3] * inv1);
        }
    }
}

// ---------------------------------------------------------------------------
// Kernel: proj GEMM. epilogue: +bias, window_reverse scatter -> out fp32
// ---------------------------------------------------------------------------
__global__ __launch_bounds__(256, 2)
void proj_hgemm_kernel(const float* __restrict__ bias, float* __restrict__ out)
{
    float acc[2][8][4] = {};
    const int m0 = blockIdx.y * 128, n0 = blockIdx.x * 128;
    hgemm_tile(g_ao, g_wp, m0, n0, acc);

    const int tid = threadIdx.x, lane = tid & 31, wid = tid >> 5;
    const int g = lane >> 2, t = lane & 3;
    const int wm = (wid & 3) * 32, wn = (wid >> 2) * 64;

    #pragma unroll
    for (int i = 0; i < 2; ++i) {
        #pragma unroll
        for (int h = 0; h < 2; ++h) {
            const int m = m0 + wm + i * 16 + h * 8 + g;
            const int win = m / NTOK, tok = m % NTOK;
            const int b = win >> 4, yw = (win >> 2) & 3, xw = win & 3;
            const int y = yw * 12 + tok / 12;
            const int x = xw * 12 + tok % 12;
            float* orow = out + ((b * 2304 + y * 48 + x) << 9);
            #pragma unroll
            for (int j = 0; j < 8; ++j) {
                const int n = n0 + wn + j * 8 + 2 * t;
                float2 v;
                v.x = acc[i][j][h * 2 + 0] + bias[n + 0];
                v.y = acc[i][j][h * 2 + 1] + bias[n + 1];
                *(float2*)&orow[n] = v;
            }
        }
    }
}

// ---------------------------------------------------------------------------
extern "C" void kernel_launch(void* const* d_in, const int* in_sizes, int n_in,
                              void* d_out, int out_size)
{
    const float* hidden = (const float*)d_in[0];
    const float* qkv_w  = (const float*)d_in[1];
    const float* qkv_b  = (const float*)d_in[2];
    const float* proj_w = (const float*)d_in[3];
    const float* proj_b = (const float*)d_in[4];
    float* out = (float*)d_out;

    convert_x_kernel<<<MTOT * 64 / 256, 256>>>(hidden);
    convert_w_kernel<<<dim3(NQKV / 32, DIM / 32), dim3(32, 8)>>>(qkv_w, 0);
    convert_w_kernel<<<dim3(DIM / 32, DIM / 32), dim3(32, 8)>>>(proj_w, 1);

    qkv_hgemm_kernel<<<dim3(NQKV / 128, MTOT / 128), 256>>>(qkv_b);

    attn_mma_kernel<<<NWIN * NHEAD, 96>>>();

    proj_hgemm_kernel<<<dim3(DIM / 128, MTOT / 128), 256>>>(proj_b, out);
}

// round 9
// speedup vs baseline: 6.1125x; 1.0117x over previous
#include <cuda_runtime.h>
#include <cuda_fp16.h>
#include <cstdint>

// ---------------------------------------------------------------------------
// Florence2 window attention — all three matmul stages on mma.sync (fp16/fp32).
// R9: hgemm mainloop uses ONE __syncthreads per K-chunk (canonical 2-stage
// cp.async pipeline order: wait -> sync -> prefetch -> compute).
// hidden (8,48,48,512), qkv_w (512,1536), proj_w (512,512)
// WINDOW=12 -> 128 windows x 144 tokens, 16 heads x 32 dim.
// ---------------------------------------------------------------------------

#define NWIN   128
#define NTOK   144
#define DIM    512
#define NHEAD  16
#define HDIM   32
#define MTOT   (NWIN * NTOK)     // 18432
#define NQKV   1536

#define SROW   72                // hgemm smem row stride in halves (144B, 9x16B)

// ---------------- scratch (device globals; device-code refs only) ----------
__device__ __align__(16) __half g_x  [MTOT * DIM];             // X [m][k]
__device__ __align__(16) __half g_wq [NQKV * DIM];             // qkv_w^T [n][k]
__device__ __align__(16) __half g_wp [DIM * DIM];              // proj_w^T [n][k]
__device__ __align__(16) __half g_qh [NWIN * NHEAD * NTOK * HDIM];  // Q*scale
__device__ __align__(16) __half g_kh [NWIN * NHEAD * NTOK * HDIM];  // K
__device__ __align__(16) __half g_vT [NWIN * NHEAD * HDIM * NTOK];  // V^T
__device__ __align__(16) __half g_ao [MTOT * DIM];             // attn out [m][k]

// ---------------- PTX helpers (sm_80-level, family-safe) -------------------
__device__ __forceinline__ uint32_t smem_u32(const void* p) {
    uint32_t a;
    asm("{ .reg .u64 t; cvta.to.shared.u64 t, %1; cvt.u32.u64 %0, t; }" : "=r"(a) : "l"(p));
    return a;
}
__device__ __forceinline__ void cp_async16(uint32_t s, const void* g) {
    asm volatile("cp.async.cg.shared.global [%0], [%1], 16;" :: "r"(s), "l"(g));
}
__device__ __forceinline__ void cp_commit() { asm volatile("cp.async.commit_group;"); }
__device__ __forceinline__ void cp_wait0()  { asm volatile("cp.async.wait_group 0;"); }

__device__ __forceinline__ void ldsm_x4(uint32_t* r, uint32_t addr) {
    asm volatile("ldmatrix.sync.aligned.m8n8.x4.shared.b16 {%0,%1,%2,%3}, [%4];"
        : "=r"(r[0]), "=r"(r[1]), "=r"(r[2]), "=r"(r[3]) : "r"(addr));
}
__device__ __forceinline__ void mma16816(float* d, const uint32_t* a,
                                         uint32_t b0, uint32_t b1) {
    asm volatile("mma.sync.aligned.m16n8k16.row.col.f32.f16.f16.f32 "
        "{%0,%1,%2,%3}, {%4,%5,%6,%7}, {%8,%9}, {%0,%1,%2,%3};"
        : "+f"(d[0]), "+f"(d[1]), "+f"(d[2]), "+f"(d[3])
        : "r"(a[0]), "r"(a[1]), "r"(a[2]), "r"(a[3]), "r"(b0), "r"(b1));
}

__device__ __forceinline__ int hidden_row_off(int m) {
    int win = m / NTOK, t = m % NTOK;
    int b = win >> 4, yw = (win >> 2) & 3, xw = win & 3;
    int y = yw * 12 + t / 12;
    int x = xw * 12 + t % 12;
    return ((b * 48 + y) * 48 + x) * DIM;
}

// ---------------------------------------------------------------------------
// conversion kernels (fp32 -> fp16)
// ---------------------------------------------------------------------------
__global__ void convert_x_kernel(const float* __restrict__ hidden) {
    int idx = blockIdx.x * 256 + threadIdx.x;       // m*64 + seg
    int m = idx >> 6, seg = idx & 63;
    const float* src = hidden + hidden_row_off(m) + seg * 8;
    float4 f0 = *(const float4*)src;
    float4 f1 = *(const float4*)(src + 4);
    __align__(16) __half h[8];
    h[0] = __float2half(f0.x); h[1] = __float2half(f0.y);
    h[2] = __float2half(f0.z); h[3] = __float2half(f0.w);
    h[4] = __float2half(f1.x); h[5] = __float2half(f1.y);
    h[6] = __float2half(f1.z); h[7] = __float2half(f1.w);
    *(uint4*)&g_x[m * DIM + seg * 8] = *(uint4*)h;
}

// transpose W [K=512][N] -> [n][512]; sel 0 -> g_wq (N=1536), 1 -> g_wp (N=512)
__global__ void convert_w_kernel(const float* __restrict__ W, int sel) {
    __shared__ float t[32][33];
    const int N = sel ? DIM : NQKV;
    __half* __restrict__ outT = sel ? g_wp : g_wq;
    int tx = threadIdx.x, ty = threadIdx.y;
    int n0 = blockIdx.x * 32, k0 = blockIdx.y * 32;
    #pragma unroll
    for (int j = 0; j < 4; ++j)
        t[ty + 8 * j][tx] = W[(k0 + ty + 8 * j) * N + n0 + tx];
    __syncthreads();
    #pragma unroll
    for (int j = 0; j < 4; ++j)
        outT[(n0 + ty + 8 * j) * DIM + k0 + tx] = __float2half(t[tx][ty + 8 * j]);
}

// ---------------------------------------------------------------------------
// HGEMM mainloop: 128x128 tile, K=512 in 8 chunks of 64.
// 2-stage cp.async pipeline, ONE __syncthreads per chunk:
//   wait_group 0 -> barrier -> prefetch(ch+1) -> compute(ch)
// 8 warps: warp tile 32(M) x 64(N). ldmatrix.x4 fragment loads.
// ---------------------------------------------------------------------------
#define BUFH (128 * SROW)        // halves per buffer (per operand)

__device__ __forceinline__ void hgemm_tile(
    const __half* __restrict__ A, const __half* __restrict__ B,
    int m0, int n0, float acc[2][8][4])
{
    __shared__ __align__(16) __half sA[2][BUFH];
    __shared__ __align__(16) __half sB[2][BUFH];

    const int tid = threadIdx.x;
    const int lane = tid & 31, wid = tid >> 5;
    const int wm = (wid & 3) * 32, wn = (wid >> 2) * 64;

    const uint32_t aBase = smem_u32(&sA[0][0]);
    const uint32_t bBase = smem_u32(&sB[0][0]);

    // ---- cp.async staging coords: 4 x 16B segments per operand per thread
    int rowv[4];
    const int uvb = (tid & 7) * 16;          // byte offset of 16B unit in row
    #pragma unroll
    for (int i = 0; i < 4; ++i) rowv[i] = 32 * i + (tid >> 3);

    uint32_t stA[4], stB[4];
    const __half* gA[4];
    const __half* gB[4];
    #pragma unroll
    for (int i = 0; i < 4; ++i) {
        stA[i] = aBase + rowv[i] * (SROW * 2) + uvb;
        stB[i] = bBase + rowv[i] * (SROW * 2) + uvb;
        gA[i] = A + (m0 + rowv[i]) * DIM + (tid & 7) * 8;
        gB[i] = B + (n0 + rowv[i]) * DIM + (tid & 7) * 8;
    }

    // ---- ldmatrix lane addressing (byte offsets)
    const int la = lane & 7;
    const int arow = wm + la + ((lane & 8) ? 8 : 0);
    const int acol = (lane & 16) ? 8 : 0;            // halves
    const int brow = wn + la + ((lane & 16) ? 8 : 0);
    const int bcol = (lane & 8) ? 8 : 0;

    const uint32_t aFrag0 = aBase + arow * (SROW * 2) + acol * 2;
    const uint32_t bFrag0 = bBase + brow * (SROW * 2) + bcol * 2;

    // prologue: chunk 0 -> buf 0
    #pragma unroll
    for (int i = 0; i < 4; ++i) {
        cp_async16(stA[i], gA[i]);
        cp_async16(stB[i], gB[i]);
    }
    cp_commit();

    #pragma unroll 1
    for (int ch = 0; ch < 8; ++ch) {
        cp_wait0();          // chunk ch landed
        __syncthreads();     // all warps done computing chunk ch-1

        if (ch < 7) {        // prefetch ch+1 into the buffer ch-1 vacated
            const uint32_t bo = ((ch + 1) & 1) * (BUFH * 2);
            const int ko = (ch + 1) * 64;
            #pragma unroll
            for (int i = 0; i < 4; ++i) {
                cp_async16(stA[i] + bo, gA[i] + ko);
                cp_async16(stB[i] + bo, gB[i] + ko);
            }
            cp_commit();
        }

        const uint32_t bo = (ch & 1) * (BUFH * 2);
        #pragma unroll
        for (int s = 0; s < 4; ++s) {
            const uint32_t kb = s * 32;              // 16 halves = 32 bytes
            uint32_t a[2][4];
            ldsm_x4(a[0], aFrag0 + bo + kb);
            ldsm_x4(a[1], aFrag0 + bo + kb + 16 * (SROW * 2));
            #pragma unroll
            for (int j2 = 0; j2 < 4; ++j2) {
                uint32_t rb[4];
                ldsm_x4(rb, bFrag0 + bo + kb + j2 * 16 * (SROW * 2));
                mma16816(acc[0][2 * j2 + 0], a[0], rb[0], rb[1]);
                mma16816(acc[0][2 * j2 + 1], a[0], rb[2], rb[3]);
                mma16816(acc[1][2 * j2 + 0], a[1], rb[0], rb[1]);
                mma16816(acc[1][2 * j2 + 1], a[1], rb[2], rb[3]);
            }
        }
    }
}

// ---------------------------------------------------------------------------
// Kernel: QKV GEMM. epilogue: +bias -> fp16 Q (pre-scaled), K, V^T
// ---------------------------------------------------------------------------
__global__ __launch_bounds__(256, 2)
void qkv_hgemm_kernel(const float* __restrict__ bias)
{
    float acc[2][8][4] = {};
    const int m0 = blockIdx.y * 128, n0 = blockIdx.x * 128;
    hgemm_tile(g_x, g_wq, m0, n0, acc);

    const int tid = threadIdx.x, lane = tid & 31, wid = tid >> 5;
    const int g = lane >> 2, t = lane & 3;
    const int wm = (wid & 3) * 32, wn = (wid >> 2) * 64;
    const float scale = 0.1767766952966369f;   // 32^-0.5

    #pragma unroll
    for (int i = 0; i < 2; ++i) {
        #pragma unroll
        for (int h = 0; h < 2; ++h) {
            const int m = m0 + wm + i * 16 + h * 8 + g;
            const int win = m / NTOK, tok = m % NTOK;
            #pragma unroll
            for (int j = 0; j < 8; ++j) {
                const int n = n0 + wn + j * 8 + 2 * t;
                const int sel = n >> 9, head = (n >> 5) & 15, d = n & 31;
                const int wh = (win << 4) + head;
                float vx = acc[i][j][h * 2 + 0] + bias[n + 0];
                float vy = acc[i][j][h * 2 + 1] + bias[n + 1];
                if (sel == 0) {
                    *(__half2*)&g_qh[(wh * NTOK + tok) * HDIM + d] =
                        __floats2half2_rn(vx * scale, vy * scale);
                } else if (sel == 1) {
                    *(__half2*)&g_kh[(wh * NTOK + tok) * HDIM + d] =
                        __floats2half2_rn(vx, vy);
                } else {
                    g_vT[(wh * HDIM + d    ) * NTOK + tok] = __float2half(vx);
                    g_vT[(wh * HDIM + d + 1) * NTOK + tok] = __float2half(vy);
                }
            }
        }
    }
}

// ---------------------------------------------------------------------------
// Kernel: tensor-core attention (proven R7). 1 block per (win,head), 96 thr.
// ---------------------------------------------------------------------------
#define QROW 40     // sQ/sK row stride (halves)
#define VROW 152    // sVT row stride (halves)

__global__ __launch_bounds__(96)
void attn_mma_kernel()
{
    __shared__ __align__(16) __half sQ[NTOK * QROW];
    __shared__ __align__(16) __half sK[NTOK * QROW];
    __shared__ __align__(16) __half sVT[HDIM * VROW];

    const int wh = blockIdx.x;
    const int tid = threadIdx.x, lane = tid & 31, wid = tid >> 5;
    const int g = lane >> 2, t = lane & 3;

    const __half* qp = g_qh + wh * (NTOK * HDIM);
    const __half* kp = g_kh + wh * (NTOK * HDIM);
    const __half* vp = g_vT + wh * (HDIM * NTOK);

    for (int seg = tid; seg < 576; seg += 96) {
        int row = seg >> 2, sub = seg & 3;
        *(uint4*)&sQ[row * QROW + sub * 8] = *(const uint4*)(qp + row * HDIM + sub * 8);
        *(uint4*)&sK[row * QROW + sub * 8] = *(const uint4*)(kp + row * HDIM + sub * 8);
        int vrow = seg / 18, vsub = seg - vrow * 18;
        *(uint4*)&sVT[vrow * VROW + vsub * 8] = *(const uint4*)(vp + vrow * NTOK + vsub * 8);
    }
    __syncthreads();

    const int win = wh >> 4, head = wh & 15;

    #pragma unroll 1
    for (int ti = 0; ti < 3; ++ti) {
        const int tile = wid * 3 + ti;
        const int r = tile * 16 + g;

        uint32_t qa[2][4];
        #pragma unroll
        for (int s = 0; s < 2; ++s) {
            const int c = s * 16 + 2 * t;
            qa[s][0] = *(const uint32_t*)&sQ[ r      * QROW + c    ];
            qa[s][1] = *(const uint32_t*)&sQ[(r + 8) * QROW + c    ];
            qa[s][2] = *(const uint32_t*)&sQ[ r      * QROW + c + 8];
            qa[s][3] = *(const uint32_t*)&sQ[(r + 8) * QROW + c + 8];
        }

        uint32_t eh[18][2];
        float sum0 = 0.f, sum1 = 0.f;
        #pragma unroll
        for (int j = 0; j < 18; ++j) {
            float sc[4] = {};
            const int rn = 8 * j + g;
            #pragma unroll
            for (int s = 0; s < 2; ++s) {
                const int c = s * 16 + 2 * t;
                uint32_t b0 = *(const uint32_t*)&sK[rn * QROW + c    ];
                uint32_t b1 = *(const uint32_t*)&sK[rn * QROW + c + 8];
                mma16816(sc, qa[s], b0, b1);
            }
            float e0 = __expf(sc[0]), e1 = __expf(sc[1]);
            float e2 = __expf(sc[2]), e3 = __expf(sc[3]);
            sum0 += e0 + e1; sum1 += e2 + e3;
            __half2 p01 = __floats2half2_rn(e0, e1);
            __half2 p23 = __floats2half2_rn(e2, e3);
            eh[j][0] = *(uint32_t*)&p01;
            eh[j][1] = *(uint32_t*)&p23;
        }
        sum0 += __shfl_xor_sync(0xffffffffu, sum0, 1);
        sum0 += __shfl_xor_sync(0xffffffffu, sum0, 2);
        sum1 += __shfl_xor_sync(0xffffffffu, sum1, 1);
        sum1 += __shfl_xor_sync(0xffffffffu, sum1, 2);

        float acc[4][4] = {};
        #pragma unroll
        for (int kk = 0; kk < 9; ++kk) {
            uint32_t a[4] = {eh[2 * kk][0], eh[2 * kk][1],
                             eh[2 * kk + 1][0], eh[2 * kk + 1][1]};
            #pragma unroll
            for (int nd = 0; nd < 4; ++nd) {
                const int rn = 8 * nd + g;
                uint32_t b0 = *(const uint32_t*)&sVT[rn * VROW + kk * 16 + 2 * t    ];
                uint32_t b1 = *(const uint32_t*)&sVT[rn * VROW + kk * 16 + 2 * t + 8];
                mma16816(acc[nd], a, b0, b1);
            }
        }

        const float inv0 = 1.f / sum0, inv1 = 1.f / sum1;
        __half* o0 = g_ao + (win * NTOK + r) * DIM + head * HDIM;
        __half* o1 = o0 + 8 * DIM;
        #pragma unroll
        for (int nd = 0; nd < 4; ++nd) {
            const int d = 8 * nd + 2 * t;
            *(__half2*)&o0[d] = __floats2half2_rn(acc[nd][0] * inv0, acc[nd][1] * inv0);
            *(__half2*)&o1[d] = __floats2half2_rn(acc[nd][2] * inv1, acc[nd][3] * inv1);
        }
    }
}

// ---------------------------------------------------------------------------
// Kernel: proj GEMM. epilogue: +bias, window_reverse scatter -> out fp32
// ---------------------------------------------------------------------------
__global__ __launch_bounds__(256, 2)
void proj_hgemm_kernel(const float* __restrict__ bias, float* __restrict__ out)
{
    float acc[2][8][4] = {};
    const int m0 = blockIdx.y * 128, n0 = blockIdx.x * 128;
    hgemm_tile(g_ao, g_wp, m0, n0, acc);

    const int tid = threadIdx.x, lane = tid & 31, wid = tid >> 5;
    const int g = lane >> 2, t = lane & 3;
    const int wm = (wid & 3) * 32, wn = (wid >> 2) * 64;

    #pragma unroll
    for (int i = 0; i < 2; ++i) {
        #pragma unroll
        for (int h = 0; h < 2; ++h) {
            const int m = m0 + wm + i * 16 + h * 8 + g;
            const int win = m / NTOK, tok = m % NTOK;
            const int b = win >> 4, yw = (win >> 2) & 3, xw = win & 3;
            const int y = yw * 12 + tok / 12;
            const int x = xw * 12 + tok % 12;
            float* orow = out + ((b * 2304 + y * 48 + x) << 9);
            #pragma unroll
            for (int j = 0; j < 8; ++j) {
                const int n = n0 + wn + j * 8 + 2 * t;
                float2 v;
                v.x = acc[i][j][h * 2 + 0] + bias[n + 0];
                v.y = acc[i][j][h * 2 + 1] + bias[n + 1];
                *(float2*)&orow[n] = v;
            }
        }
    }
}

// ---------------------------------------------------------------------------
extern "C" void kernel_launch(void* const* d_in, const int* in_sizes, int n_in,
                              void* d_out, int out_size)
{
    const float* hidden = (const float*)d_in[0];
    const float* qkv_w  = (const float*)d_in[1];
    const float* qkv_b  = (const float*)d_in[2];
    const float* proj_w = (const float*)d_in[3];
    const float* proj_b = (const float*)d_in[4];
    float* out = (float*)d_out;

    convert_x_kernel<<<MTOT * 64 / 256, 256>>>(hidden);
    convert_w_kernel<<<dim3(NQKV / 32, DIM / 32), dim3(32, 8)>>>(qkv_w, 0);
    convert_w_kernel<<<dim3(DIM / 32, DIM / 32), dim3(32, 8)>>>(proj_w, 1);

    qkv_hgemm_kernel<<<dim3(NQKV / 128, MTOT / 128), 256>>>(qkv_b);

    attn_mma_kernel<<<NWIN * NHEAD, 96>>>();

    proj_hgemm_kernel<<<dim3(DIM / 128, MTOT / 128), 256>>>(proj_b, out);
}